// round 5
// baseline (speedup 1.0000x reference)
#include <cuda_runtime.h>
#include <cstddef>
#include <cstdint>

#define NNODES 100000
#define MAXE   1600000
#define SCAN_BLK 1024
#define SCAN_NB  ((NNODES + SCAN_BLK - 1) / SCAN_BLK)   // 98

// ---------------- scratch (static device globals; no allocations) ----------------
__device__ __align__(16) float g_bufA[(size_t)NNODES * 128];
__device__ __align__(16) float g_bufB[(size_t)NNODES * 128];
__device__ int   g_cnt[NNODES];
__device__ int   g_wp[NNODES];
__device__ int   g_row_ptr[NNODES + 1];
__device__ int   g_col[MAXE];
__device__ unsigned long long g_blkp[SCAN_NB];
__device__ float g_invdeg[NNODES];
__device__ __align__(16) float g_stats[512];   // layer1: [0,256) ; layer2: [256,512)
__device__ __align__(16) float g_ss[256];      // [scale[128], shift[128]]
__device__ int   g_is64 = 1;                   // module-init; only 0 is ever written

// ---------------- init: zero counters/flags/stats + dtype detect ----------------
__global__ void k_init(const unsigned int* __restrict__ w) {
    int i = blockIdx.x * blockDim.x + threadIdx.x;
    if (i < NNODES) g_cnt[i] = 0;
    if (i < SCAN_NB) g_blkp[i] = 0ull;
    if (i < 512) g_stats[i] = 0.f;
    if (i < 2048) {
        if (w[2 * i + 1] != 0u) g_is64 = 0;   // benign race: only writes 0
    }
}

__global__ void k_hist(const void* __restrict__ ei, int E) {
    int is64 = g_is64;
    int i = blockIdx.x * blockDim.x + threadIdx.x;
    int stride = gridDim.x * blockDim.x;
    if (is64) {
        const long long* p = (const long long*)ei;
        for (; i < E; i += stride) atomicAdd(&g_cnt[(int)p[i]], 1);
    } else {
        const int* p = (const int*)ei;
        for (; i < E; i += stride) atomicAdd(&g_cnt[p[i]], 1);
    }
}

// ---------------- single-kernel decoupled scan over g_cnt ----------------
__global__ void k_scan() {
    __shared__ int wsum[32];
    __shared__ int blk_off;
    int tid = threadIdx.x, lane = tid & 31, w = tid >> 5;
    int bid = blockIdx.x;
    if (tid == 0) blk_off = 0;

    int i = bid * SCAN_BLK + tid;
    int v = (i < NNODES) ? g_cnt[i] : 0;
    int s = v;
    #pragma unroll
    for (int o = 1; o < 32; o <<= 1) {
        int t = __shfl_up_sync(0xffffffffu, s, o);
        if (lane >= o) s += t;
    }
    if (lane == 31) wsum[w] = s;
    __syncthreads();
    if (w == 0) {
        int x = wsum[lane];
        int ss = x;
        #pragma unroll
        for (int o = 1; o < 32; o <<= 1) {
            int t = __shfl_up_sync(0xffffffffu, ss, o);
            if (lane >= o) ss += t;
        }
        wsum[lane] = ss - x;
        if (lane == 31) {
            atomicExch(&g_blkp[bid], (((unsigned long long)(unsigned)ss) << 1) | 1ull);
        }
    }
    __syncthreads();

    if (tid < bid) {
        const volatile unsigned long long* p = &g_blkp[tid];
        unsigned long long pv;
        do { pv = *p; } while (!(pv & 1ull));
        atomicAdd(&blk_off, (int)(pv >> 1));
    }
    __syncthreads();

    int incl = s + wsum[w] + blk_off;
    if (i < NNODES) {
        g_row_ptr[i + 1] = incl;
        g_wp[i] = incl - v;
        g_invdeg[i] = 1.0f / ((float)v + 1e-6f);
        if (i == 0) g_row_ptr[0] = 0;
    }
}

__global__ void k_fill(const void* __restrict__ ei, int E) {
    int is64 = g_is64;
    int i = blockIdx.x * blockDim.x + threadIdx.x;
    int stride = gridDim.x * blockDim.x;
    if (is64) {
        const long long* p = (const long long*)ei;
        for (; i < E; i += stride) {
            int r = (int)p[i];
            int c = (int)p[E + i];
            int q = atomicAdd(&g_wp[r], 1);
            g_col[q] = c;
        }
    } else {
        const int* p = (const int*)ei;
        for (; i < E; i += stride) {
            int r = p[i];
            int c = p[E + i];
            int q = atomicAdd(&g_wp[r], 1);
            g_col[q] = c;
        }
    }
}

// ---------------- aggregation kernels (warp per node, 4-wide edge unroll) ------
__global__ void k_agg64(const float* __restrict__ src, float* __restrict__ dst) {
    int gw = (blockIdx.x * blockDim.x + threadIdx.x) >> 5;
    if (gw >= NNODES) return;
    int lane = threadIdx.x & 31;
    int beg = g_row_ptr[gw], end = g_row_ptr[gw + 1];
    float2 a0 = {0.f, 0.f}, a1 = {0.f, 0.f};
    const float2* s2 = (const float2*)src;
    int e = beg;
    for (; e + 3 < end; e += 4) {
        int c0 = __ldg(&g_col[e]),     c1 = __ldg(&g_col[e + 1]);
        int c2 = __ldg(&g_col[e + 2]), c3 = __ldg(&g_col[e + 3]);
        float2 v0 = __ldg(s2 + (size_t)c0 * 32 + lane);
        float2 v1 = __ldg(s2 + (size_t)c1 * 32 + lane);
        float2 v2 = __ldg(s2 + (size_t)c2 * 32 + lane);
        float2 v3 = __ldg(s2 + (size_t)c3 * 32 + lane);
        a0.x += v0.x; a0.y += v0.y;
        a1.x += v1.x; a1.y += v1.y;
        a0.x += v2.x; a0.y += v2.y;
        a1.x += v3.x; a1.y += v3.y;
    }
    for (; e < end; e++) {
        int c0 = __ldg(&g_col[e]);
        float2 v0 = __ldg(s2 + (size_t)c0 * 32 + lane);
        a0.x += v0.x; a0.y += v0.y;
    }
    float w = g_invdeg[gw];
    float2 r;
    r.x = (a0.x + a1.x) * w;
    r.y = (a0.y + a1.y) * w;
    ((float2*)dst)[(size_t)gw * 32 + lane] = r;
}

__global__ void k_agg128_bn(const float* __restrict__ src, float* __restrict__ dst) {
    int gw = (blockIdx.x * blockDim.x + threadIdx.x) >> 5;
    if (gw >= NNODES) return;
    int lane = threadIdx.x & 31;
    float4 sc = *(const float4*)&g_ss[lane * 4];
    float4 sh = *(const float4*)&g_ss[128 + lane * 4];
    int beg = g_row_ptr[gw], end = g_row_ptr[gw + 1];
    float4 a0 = {0.f, 0.f, 0.f, 0.f}, a1 = {0.f, 0.f, 0.f, 0.f};
    const float4* s4 = (const float4*)src;
    int e = beg;
    for (; e + 3 < end; e += 4) {
        int c0 = __ldg(&g_col[e]),     c1 = __ldg(&g_col[e + 1]);
        int c2 = __ldg(&g_col[e + 2]), c3 = __ldg(&g_col[e + 3]);
        float4 v0 = __ldg(s4 + (size_t)c0 * 32 + lane);
        float4 v1 = __ldg(s4 + (size_t)c1 * 32 + lane);
        float4 v2 = __ldg(s4 + (size_t)c2 * 32 + lane);
        float4 v3 = __ldg(s4 + (size_t)c3 * 32 + lane);
        a0.x += fmaxf(fmaf(v0.x, sc.x, sh.x), 0.f);
        a0.y += fmaxf(fmaf(v0.y, sc.y, sh.y), 0.f);
        a0.z += fmaxf(fmaf(v0.z, sc.z, sh.z), 0.f);
        a0.w += fmaxf(fmaf(v0.w, sc.w, sh.w), 0.f);
        a1.x += fmaxf(fmaf(v1.x, sc.x, sh.x), 0.f);
        a1.y += fmaxf(fmaf(v1.y, sc.y, sh.y), 0.f);
        a1.z += fmaxf(fmaf(v1.z, sc.z, sh.z), 0.f);
        a1.w += fmaxf(fmaf(v1.w, sc.w, sh.w), 0.f);
        a0.x += fmaxf(fmaf(v2.x, sc.x, sh.x), 0.f);
        a0.y += fmaxf(fmaf(v2.y, sc.y, sh.y), 0.f);
        a0.z += fmaxf(fmaf(v2.z, sc.z, sh.z), 0.f);
        a0.w += fmaxf(fmaf(v2.w, sc.w, sh.w), 0.f);
        a1.x += fmaxf(fmaf(v3.x, sc.x, sh.x), 0.f);
        a1.y += fmaxf(fmaf(v3.y, sc.y, sh.y), 0.f);
        a1.z += fmaxf(fmaf(v3.z, sc.z, sh.z), 0.f);
        a1.w += fmaxf(fmaf(v3.w, sc.w, sh.w), 0.f);
    }
    for (; e < end; e++) {
        int c0 = __ldg(&g_col[e]);
        float4 v0 = __ldg(s4 + (size_t)c0 * 32 + lane);
        a0.x += fmaxf(fmaf(v0.x, sc.x, sh.x), 0.f);
        a0.y += fmaxf(fmaf(v0.y, sc.y, sh.y), 0.f);
        a0.z += fmaxf(fmaf(v0.z, sc.z, sh.z), 0.f);
        a0.w += fmaxf(fmaf(v0.w, sc.w, sh.w), 0.f);
    }
    float w = g_invdeg[gw];
    float4 r;
    r.x = (a0.x + a1.x) * w;
    r.y = (a0.y + a1.y) * w;
    r.z = (a0.z + a1.z) * w;
    r.w = (a0.w + a1.w) * w;
    ((float4*)dst)[(size_t)gw * 32 + lane] = r;
}

__global__ void k_agg64_bias(const float* __restrict__ src,
                             const float* __restrict__ b3,
                             float* __restrict__ dst) {
    int gw = (blockIdx.x * blockDim.x + threadIdx.x) >> 5;
    if (gw >= NNODES) return;
    int lane = threadIdx.x & 31;
    float2 bb = __ldg((const float2*)b3 + lane);
    int beg = g_row_ptr[gw], end = g_row_ptr[gw + 1];
    float2 a0 = {0.f, 0.f}, a1 = {0.f, 0.f};
    const float2* s2 = (const float2*)src;
    int e = beg;
    for (; e + 3 < end; e += 4) {
        int c0 = __ldg(&g_col[e]),     c1 = __ldg(&g_col[e + 1]);
        int c2 = __ldg(&g_col[e + 2]), c3 = __ldg(&g_col[e + 3]);
        float2 v0 = __ldg(s2 + (size_t)c0 * 32 + lane);
        float2 v1 = __ldg(s2 + (size_t)c1 * 32 + lane);
        float2 v2 = __ldg(s2 + (size_t)c2 * 32 + lane);
        float2 v3 = __ldg(s2 + (size_t)c3 * 32 + lane);
        a0.x += v0.x; a0.y += v0.y;
        a1.x += v1.x; a1.y += v1.y;
        a0.x += v2.x; a0.y += v2.y;
        a1.x += v3.x; a1.y += v3.y;
    }
    for (; e < end; e++) {
        int c0 = __ldg(&g_col[e]);
        float2 v0 = __ldg(s2 + (size_t)c0 * 32 + lane);
        a0.x += v0.x; a0.y += v0.y;
    }
    float w = g_invdeg[gw];
    float2 r;
    r.x = fmaf(a0.x + a1.x, w, bb.x);
    r.y = fmaf(a0.y + a1.y, w, bb.y);
    ((float2*)dst)[(size_t)gw * 32 + lane] = r;
}

// ---------------- tensor-core GEMM (3xTF32 mma.sync) ----------------
// out[n][m] = sum_k A[n][k]*W[m][k] (+bias); opt BN+relu on A; opt col stats.
__device__ __forceinline__ float f2tf32(float x) {
    float r;
    asm("cvt.rna.tf32.f32 %0, %1;" : "=f"(r) : "f"(x));
    return r;
}

__device__ __forceinline__ void mma8(float* c, uint32_t a0, uint32_t a1,
                                     uint32_t a2, uint32_t a3,
                                     uint32_t b0, uint32_t b1) {
    asm volatile(
        "mma.sync.aligned.m16n8k8.row.col.f32.tf32.tf32.f32 "
        "{%0,%1,%2,%3},{%4,%5,%6,%7},{%8,%9},{%0,%1,%2,%3};"
        : "+f"(c[0]), "+f"(c[1]), "+f"(c[2]), "+f"(c[3])
        : "r"(a0), "r"(a1), "r"(a2), "r"(a3), "r"(b0), "r"(b1));
}

template <int KD, int MD, bool BN_IN, bool STATS, bool BIAS, int SOFF>
__global__ void __launch_bounds__(256)
k_gemm_tc(const float* __restrict__ A, const float* __restrict__ W,
          const float* __restrict__ bias, float* __restrict__ out, int nrows) {
    constexpr int KC = 32, BM = 128;
    constexpr int NT = MD / 8;          // n-tiles per warp
    constexpr int BMP = BM + 4;         // float2-row pad -> conflict-free frags
    constexpr int MDP = MD + 4;

    extern __shared__ __align__(16) float2 sm2[];
    float2* sAh = sm2;                  // [16][BMP] pairs (k, k+4)
    float2* sAl = sAh + 16 * BMP;
    float2* sBh = sAl + 16 * BMP;       // [16][MDP]
    float2* sBl = sBh + 16 * MDP;
    float*  s_sum = (float*)(sBl + 16 * MDP);
    float*  s_sq  = s_sum + MD;

    int tid = threadIdx.x;
    int lane = tid & 31, warp = tid >> 5;
    int row0 = blockIdx.x * BM;
    int g = lane >> 2;                  // groupID
    int kq = lane & 3;                  // threadID_in_group

    if (STATS && tid < MD) { s_sum[tid] = 0.f; s_sq[tid] = 0.f; }

    float acc[NT][4];
    #pragma unroll
    for (int j = 0; j < NT; j++) {
        acc[j][0] = 0.f; acc[j][1] = 0.f; acc[j][2] = 0.f; acc[j][3] = 0.f;
    }

    for (int kc = 0; kc < KD; kc += KC) {
        __syncthreads();
        // A tile: BM x KC, split hi/lo, packed as (k, k+4) float2 pairs
        #pragma unroll
        for (int i = 0; i < (BM * KC) / 256; i++) {
            int idx = tid + i * 256;
            int r = idx >> 5, kk = idx & 31;
            int gr = row0 + r;
            float v = (gr < nrows) ? __ldg(&A[(size_t)gr * KD + kc + kk]) : 0.f;
            if (BN_IN) {
                v = fmaxf(fmaf(v, g_ss[kc + kk], g_ss[128 + kc + kk]), 0.f);
            }
            float hi = f2tf32(v);
            float lo = f2tf32(v - hi);
            int kp = (kk >> 3) * 4 + (kk & 3);
            int half = (kk >> 2) & 1;
            ((float*)&sAh[kp * BMP + r])[half] = hi;
            ((float*)&sAl[kp * BMP + r])[half] = lo;
        }
        // W tile: MD x KC (B[k][n] = W[n][k]), same packing
        #pragma unroll
        for (int i = 0; i < (MD * KC) / 256; i++) {
            int idx = tid + i * 256;
            int c = idx >> 5, kk = idx & 31;
            float v = __ldg(&W[(size_t)c * KD + kc + kk]);
            float hi = f2tf32(v);
            float lo = f2tf32(v - hi);
            int kp = (kk >> 3) * 4 + (kk & 3);
            int half = (kk >> 2) & 1;
            ((float*)&sBh[kp * MDP + c])[half] = hi;
            ((float*)&sBl[kp * MDP + c])[half] = lo;
        }
        __syncthreads();

        #pragma unroll
        for (int s = 0; s < 4; s++) {
            int kp = s * 4 + kq;
            int ra = warp * 16 + g;
            float2 aH0 = sAh[kp * BMP + ra];
            float2 aH1 = sAh[kp * BMP + ra + 8];
            float2 aL0 = sAl[kp * BMP + ra];
            float2 aL1 = sAl[kp * BMP + ra + 8];
            uint32_t ah0 = __float_as_uint(aH0.x), ah1 = __float_as_uint(aH1.x);
            uint32_t ah2 = __float_as_uint(aH0.y), ah3 = __float_as_uint(aH1.y);
            uint32_t al0 = __float_as_uint(aL0.x), al1 = __float_as_uint(aL1.x);
            uint32_t al2 = __float_as_uint(aL0.y), al3 = __float_as_uint(aL1.y);
            #pragma unroll
            for (int j = 0; j < NT; j++) {
                float2 bH = sBh[kp * MDP + 8 * j + g];
                float2 bL = sBl[kp * MDP + 8 * j + g];
                uint32_t bh0 = __float_as_uint(bH.x), bh1 = __float_as_uint(bH.y);
                uint32_t bl0 = __float_as_uint(bL.x), bl1 = __float_as_uint(bL.y);
                mma8(acc[j], ah0, ah1, ah2, ah3, bh0, bh1);
                mma8(acc[j], al0, al1, al2, al3, bh0, bh1);
                mma8(acc[j], ah0, ah1, ah2, ah3, bl0, bl1);
            }
        }
    }

    // epilogue: bias, store, optional column stats
    int r0 = row0 + warp * 16 + g;
    int r1 = r0 + 8;
    bool ok0 = r0 < nrows, ok1 = r1 < nrows;

    #pragma unroll
    for (int j = 0; j < NT; j++) {
        int n0 = 8 * j + 2 * kq;
        float b0 = BIAS ? __ldg(&bias[n0]) : 0.f;
        float b1 = BIAS ? __ldg(&bias[n0 + 1]) : 0.f;
        float h00 = acc[j][0] + b0, h01 = acc[j][1] + b1;
        float h10 = acc[j][2] + b0, h11 = acc[j][3] + b1;
        if (ok0) *(float2*)&out[(size_t)r0 * MD + n0] = make_float2(h00, h01);
        if (ok1) *(float2*)&out[(size_t)r1 * MD + n0] = make_float2(h10, h11);
        if (STATS) {
            float s0 = (ok0 ? h00 : 0.f) + (ok1 ? h10 : 0.f);
            float s1 = (ok0 ? h01 : 0.f) + (ok1 ? h11 : 0.f);
            float q0 = (ok0 ? h00 * h00 : 0.f) + (ok1 ? h10 * h10 : 0.f);
            float q1 = (ok0 ? h01 * h01 : 0.f) + (ok1 ? h11 * h11 : 0.f);
            atomicAdd(&s_sum[n0], s0);
            atomicAdd(&s_sum[n0 + 1], s1);
            atomicAdd(&s_sq[n0], q0);
            atomicAdd(&s_sq[n0 + 1], q1);
        }
    }

    if (STATS) {
        __syncthreads();
        if (tid < MD) {
            atomicAdd(&g_stats[SOFF + tid], s_sum[tid]);
            atomicAdd(&g_stats[SOFF + 128 + tid], s_sq[tid]);
        }
    }
}

__global__ void k_bnfin(const float* __restrict__ gamma,
                        const float* __restrict__ beta, int soff) {
    int c = threadIdx.x;
    if (c < 128) {
        float s = g_stats[soff + c], q = g_stats[soff + 128 + c];
        float mean = s * (1.0f / NNODES);
        float var = q * (1.0f / NNODES) - mean * mean;
        float sc = __ldg(&gamma[c]) * rsqrtf(var + 1e-5f);
        g_ss[c] = sc;
        g_ss[128 + c] = fmaf(-mean, sc, __ldg(&beta[c]));
    }
}

// ---------------- launch ----------------
static inline int smem_bytes(int MD) {
    // 2*(16*BMP) A pairs + 2*(16*MDP) B pairs, float2 each, + 2*MD stats floats
    int BMP = 132, MDP = MD + 4;
    return (2 * 16 * BMP + 2 * 16 * MDP) * 8 + 2 * MD * 4;
}

extern "C" void kernel_launch(void* const* d_in, const int* in_sizes, int n_in,
                              void* d_out, int out_size) {
    const float* x   = (const float*)d_in[0];
    const void*  ei  = d_in[1];
    const float* W1  = (const float*)d_in[2];
    const float* b1  = (const float*)d_in[3];
    const float* ga1 = (const float*)d_in[4];
    const float* be1 = (const float*)d_in[5];
    const float* W2  = (const float*)d_in[6];
    const float* b2  = (const float*)d_in[7];
    const float* ga2 = (const float*)d_in[8];
    const float* be2 = (const float*)d_in[9];
    const float* W3  = (const float*)d_in[10];
    const float* b3  = (const float*)d_in[11];
    float* out = (float*)d_out;

    int E = in_sizes[1] / 2;
    if (E > MAXE) E = MAXE;

    float *bufA, *bufB;
    cudaGetSymbolAddress((void**)&bufA, g_bufA);
    cudaGetSymbolAddress((void**)&bufB, g_bufB);

    const int sm128 = smem_bytes(128);
    const int sm64  = smem_bytes(64);
    cudaFuncSetAttribute((const void*)k_gemm_tc<64, 128, false, true, true, 0>,
                         cudaFuncAttributeMaxDynamicSharedMemorySize, sm128);
    cudaFuncSetAttribute((const void*)k_gemm_tc<128, 128, false, true, true, 256>,
                         cudaFuncAttributeMaxDynamicSharedMemorySize, sm128);
    cudaFuncSetAttribute((const void*)k_gemm_tc<128, 64, true, false, false, 0>,
                         cudaFuncAttributeMaxDynamicSharedMemorySize, sm64);

    // CSR build
    k_init<<<SCAN_NB, SCAN_BLK>>>((const unsigned int*)ei);
    k_hist<<<1024, 256>>>(ei, E);
    k_scan<<<SCAN_NB, SCAN_BLK>>>();
    k_fill<<<1024, 256>>>(ei, E);

    const int aggBlocks = (NNODES * 32 + 255) / 256;
    const int gemmBlocks = (NNODES + 127) / 128;

    // layer 1: agg(x) -> bufA[N,64]; GEMM1 (+b1, stats->0) -> bufB[N,128]
    k_agg64<<<aggBlocks, 256>>>(x, bufA);
    k_gemm_tc<64, 128, false, true, true, 0><<<gemmBlocks, 256, sm128>>>(bufA, W1, b1, bufB, NNODES);
    k_bnfin<<<1, 128>>>(ga1, be1, 0);

    // layer 2: agg(relu(BN1(h1))) -> bufA[N,128]; GEMM2 (+b2, stats->256) -> bufB[N,128]
    k_agg128_bn<<<aggBlocks, 256>>>(bufB, bufA);
    k_gemm_tc<128, 128, false, true, true, 256><<<gemmBlocks, 256, sm128>>>(bufA, W2, b2, bufB, NNODES);
    k_bnfin<<<1, 128>>>(ga2, be2, 256);

    // layer 3 (reordered): t = relu(BN2(h2)) @ W3^T -> bufA[N,64]; agg(t)+b3 -> out
    k_gemm_tc<128, 64, true, false, false, 0><<<gemmBlocks, 256, sm64>>>(bufB, W3, nullptr, bufA, NNODES);
    k_agg64_bias<<<aggBlocks, 256>>>(bufA, b3, out);
}

// round 6
// speedup vs baseline: 1.1572x; 1.1572x over previous
#include <cuda_runtime.h>
#include <cuda_fp16.h>
#include <cstddef>
#include <cstdint>

#define NNODES 100000
#define MAXE   1600000
#define SCAN_BLK 1024
#define SCAN_NB  ((NNODES + SCAN_BLK - 1) / SCAN_BLK)   // 98

// ---------------- scratch (static device globals; no allocations) ----------------
__device__ __align__(16) float  g_bufA[(size_t)NNODES * 128];
__device__ __align__(16) float  g_bufB[(size_t)NNODES * 128];
__device__ __align__(16) __half g_bufH[(size_t)NNODES * 128];
__device__ int   g_cnt[NNODES];
__device__ int   g_wp[NNODES];
__device__ int   g_row_ptr[NNODES + 1];
__device__ int   g_col[MAXE];
__device__ unsigned long long g_blkp[SCAN_NB];
__device__ float g_invdeg[NNODES];
__device__ __align__(16) float g_stats[512];   // layer1: [0,256) ; layer2: [256,512)
__device__ __align__(16) float g_ss[256];      // [scale[128], shift[128]]
__device__ int   g_is64 = 1;                   // module-init; only 0 is ever written

// ---------------- init: zero counters/flags/stats + dtype detect ----------------
__global__ void k_init(const unsigned int* __restrict__ w) {
    int i = blockIdx.x * blockDim.x + threadIdx.x;
    if (i < NNODES) g_cnt[i] = 0;
    if (i < SCAN_NB) g_blkp[i] = 0ull;
    if (i < 512) g_stats[i] = 0.f;
    if (i < 2048) {
        if (w[2 * i + 1] != 0u) g_is64 = 0;   // benign race: only writes 0
    }
}

__global__ void k_hist(const void* __restrict__ ei, int E) {
    int is64 = g_is64;
    int i = blockIdx.x * blockDim.x + threadIdx.x;
    int stride = gridDim.x * blockDim.x;
    if (is64) {
        const long long* p = (const long long*)ei;
        for (; i < E; i += stride) atomicAdd(&g_cnt[(int)p[i]], 1);
    } else {
        const int* p = (const int*)ei;
        for (; i < E; i += stride) atomicAdd(&g_cnt[p[i]], 1);
    }
}

// ---------------- single-kernel decoupled scan over g_cnt ----------------
__global__ void k_scan() {
    __shared__ int wsum[32];
    __shared__ int blk_off;
    int tid = threadIdx.x, lane = tid & 31, w = tid >> 5;
    int bid = blockIdx.x;
    if (tid == 0) blk_off = 0;

    int i = bid * SCAN_BLK + tid;
    int v = (i < NNODES) ? g_cnt[i] : 0;
    int s = v;
    #pragma unroll
    for (int o = 1; o < 32; o <<= 1) {
        int t = __shfl_up_sync(0xffffffffu, s, o);
        if (lane >= o) s += t;
    }
    if (lane == 31) wsum[w] = s;
    __syncthreads();
    if (w == 0) {
        int x = wsum[lane];
        int ss = x;
        #pragma unroll
        for (int o = 1; o < 32; o <<= 1) {
            int t = __shfl_up_sync(0xffffffffu, ss, o);
            if (lane >= o) ss += t;
        }
        wsum[lane] = ss - x;
        if (lane == 31) {
            atomicExch(&g_blkp[bid], (((unsigned long long)(unsigned)ss) << 1) | 1ull);
        }
    }
    __syncthreads();

    if (tid < bid) {
        const volatile unsigned long long* p = &g_blkp[tid];
        unsigned long long pv;
        do { pv = *p; } while (!(pv & 1ull));
        atomicAdd(&blk_off, (int)(pv >> 1));
    }
    __syncthreads();

    int incl = s + wsum[w] + blk_off;
    if (i < NNODES) {
        g_row_ptr[i + 1] = incl;
        g_wp[i] = incl - v;
        g_invdeg[i] = 1.0f / ((float)v + 1e-6f);
        if (i == 0) g_row_ptr[0] = 0;
    }
}

__global__ void k_fill(const void* __restrict__ ei, int E) {
    int is64 = g_is64;
    int i = blockIdx.x * blockDim.x + threadIdx.x;
    int stride = gridDim.x * blockDim.x;
    if (is64) {
        const long long* p = (const long long*)ei;
        for (; i < E; i += stride) {
            int r = (int)p[i];
            int c = (int)p[E + i];
            int q = atomicAdd(&g_wp[r], 1);
            g_col[q] = c;
        }
    } else {
        const int* p = (const int*)ei;
        for (; i < E; i += stride) {
            int r = p[i];
            int c = p[E + i];
            int q = atomicAdd(&g_wp[r], 1);
            g_col[q] = c;
        }
    }
}

// ---------------- fp32 -> fp16 convert (x [N,64]) ----------------
__global__ void k_x2h(const float* __restrict__ src, __half* __restrict__ dst, int n) {
    int i = blockIdx.x * blockDim.x + threadIdx.x;           // half2 index
    int stride = gridDim.x * blockDim.x;
    const float2* s2 = (const float2*)src;
    __half2* d2 = (__half2*)dst;
    for (; i < n; i += stride) {
        float2 v = __ldg(s2 + i);
        d2[i] = __floats2half2_rn(v.x, v.y);
    }
}

// ---------------- aggregation kernels (warp per node, fp16 gather) ------
// 64-dim: one half2 per lane -> one 128B line per edge
__global__ void k_agg64h(const __half* __restrict__ src, float* __restrict__ dst) {
    int gw = (blockIdx.x * blockDim.x + threadIdx.x) >> 5;
    if (gw >= NNODES) return;
    int lane = threadIdx.x & 31;
    int beg = g_row_ptr[gw], end = g_row_ptr[gw + 1];
    float2 a0 = {0.f, 0.f}, a1 = {0.f, 0.f};
    const __half2* s2 = (const __half2*)src;
    int e = beg;
    for (; e + 3 < end; e += 4) {
        int c0 = __ldg(&g_col[e]),     c1 = __ldg(&g_col[e + 1]);
        int c2 = __ldg(&g_col[e + 2]), c3 = __ldg(&g_col[e + 3]);
        float2 v0 = __half22float2(__ldg(s2 + (size_t)c0 * 32 + lane));
        float2 v1 = __half22float2(__ldg(s2 + (size_t)c1 * 32 + lane));
        float2 v2 = __half22float2(__ldg(s2 + (size_t)c2 * 32 + lane));
        float2 v3 = __half22float2(__ldg(s2 + (size_t)c3 * 32 + lane));
        a0.x += v0.x; a0.y += v0.y;
        a1.x += v1.x; a1.y += v1.y;
        a0.x += v2.x; a0.y += v2.y;
        a1.x += v3.x; a1.y += v3.y;
    }
    for (; e < end; e++) {
        int c0 = __ldg(&g_col[e]);
        float2 v0 = __half22float2(__ldg(s2 + (size_t)c0 * 32 + lane));
        a0.x += v0.x; a0.y += v0.y;
    }
    float w = g_invdeg[gw];
    float2 r;
    r.x = (a0.x + a1.x) * w;
    r.y = (a0.y + a1.y) * w;
    ((float2*)dst)[(size_t)gw * 32 + lane] = r;
}

// 128-dim fp16 gather + BN(scale/shift)+relu on the fly
__global__ void k_agg128h_bn(const __half* __restrict__ src, float* __restrict__ dst) {
    int gw = (blockIdx.x * blockDim.x + threadIdx.x) >> 5;
    if (gw >= NNODES) return;
    int lane = threadIdx.x & 31;
    float4 sc = *(const float4*)&g_ss[lane * 4];
    float4 sh = *(const float4*)&g_ss[128 + lane * 4];
    int beg = g_row_ptr[gw], end = g_row_ptr[gw + 1];
    float4 a0 = {0.f, 0.f, 0.f, 0.f}, a1 = {0.f, 0.f, 0.f, 0.f};
    const uint2* s8 = (const uint2*)src;   // 4 halves per lane, row = 32 uint2
    int e = beg;
    for (; e + 1 < end; e += 2) {
        int c0 = __ldg(&g_col[e]), c1 = __ldg(&g_col[e + 1]);
        uint2 u0 = __ldg(s8 + (size_t)c0 * 32 + lane);
        uint2 u1 = __ldg(s8 + (size_t)c1 * 32 + lane);
        float2 p00 = __half22float2(*(__half2*)&u0.x);
        float2 p01 = __half22float2(*(__half2*)&u0.y);
        float2 p10 = __half22float2(*(__half2*)&u1.x);
        float2 p11 = __half22float2(*(__half2*)&u1.y);
        a0.x += fmaxf(fmaf(p00.x, sc.x, sh.x), 0.f);
        a0.y += fmaxf(fmaf(p00.y, sc.y, sh.y), 0.f);
        a0.z += fmaxf(fmaf(p01.x, sc.z, sh.z), 0.f);
        a0.w += fmaxf(fmaf(p01.y, sc.w, sh.w), 0.f);
        a1.x += fmaxf(fmaf(p10.x, sc.x, sh.x), 0.f);
        a1.y += fmaxf(fmaf(p10.y, sc.y, sh.y), 0.f);
        a1.z += fmaxf(fmaf(p11.x, sc.z, sh.z), 0.f);
        a1.w += fmaxf(fmaf(p11.y, sc.w, sh.w), 0.f);
    }
    if (e < end) {
        int c0 = __ldg(&g_col[e]);
        uint2 u0 = __ldg(s8 + (size_t)c0 * 32 + lane);
        float2 p00 = __half22float2(*(__half2*)&u0.x);
        float2 p01 = __half22float2(*(__half2*)&u0.y);
        a0.x += fmaxf(fmaf(p00.x, sc.x, sh.x), 0.f);
        a0.y += fmaxf(fmaf(p00.y, sc.y, sh.y), 0.f);
        a0.z += fmaxf(fmaf(p01.x, sc.z, sh.z), 0.f);
        a0.w += fmaxf(fmaf(p01.y, sc.w, sh.w), 0.f);
    }
    float w = g_invdeg[gw];
    float4 r;
    r.x = (a0.x + a1.x) * w;
    r.y = (a0.y + a1.y) * w;
    r.z = (a0.z + a1.z) * w;
    r.w = (a0.w + a1.w) * w;
    ((float4*)dst)[(size_t)gw * 32 + lane] = r;
}

// final: fp16 gather of t [N,64], add bias b3 -> d_out (fp32)
__global__ void k_agg64h_bias(const __half* __restrict__ src,
                              const float* __restrict__ b3,
                              float* __restrict__ dst) {
    int gw = (blockIdx.x * blockDim.x + threadIdx.x) >> 5;
    if (gw >= NNODES) return;
    int lane = threadIdx.x & 31;
    float2 bb = __ldg((const float2*)b3 + lane);
    int beg = g_row_ptr[gw], end = g_row_ptr[gw + 1];
    float2 a0 = {0.f, 0.f}, a1 = {0.f, 0.f};
    const __half2* s2 = (const __half2*)src;
    int e = beg;
    for (; e + 3 < end; e += 4) {
        int c0 = __ldg(&g_col[e]),     c1 = __ldg(&g_col[e + 1]);
        int c2 = __ldg(&g_col[e + 2]), c3 = __ldg(&g_col[e + 3]);
        float2 v0 = __half22float2(__ldg(s2 + (size_t)c0 * 32 + lane));
        float2 v1 = __half22float2(__ldg(s2 + (size_t)c1 * 32 + lane));
        float2 v2 = __half22float2(__ldg(s2 + (size_t)c2 * 32 + lane));
        float2 v3 = __half22float2(__ldg(s2 + (size_t)c3 * 32 + lane));
        a0.x += v0.x; a0.y += v0.y;
        a1.x += v1.x; a1.y += v1.y;
        a0.x += v2.x; a0.y += v2.y;
        a1.x += v3.x; a1.y += v3.y;
    }
    for (; e < end; e++) {
        int c0 = __ldg(&g_col[e]);
        float2 v0 = __half22float2(__ldg(s2 + (size_t)c0 * 32 + lane));
        a0.x += v0.x; a0.y += v0.y;
    }
    float w = g_invdeg[gw];
    float2 r;
    r.x = fmaf(a0.x + a1.x, w, bb.x);
    r.y = fmaf(a0.y + a1.y, w, bb.y);
    ((float2*)dst)[(size_t)gw * 32 + lane] = r;
}

// ---------------- GEMM (FFMA): out[n][m] = sum_k A[n][k]*W[m][k] (+bias),
// opt BN+relu on A, opt col stats, opt fp16 output ----------------
template <int KD, int MD, int TN, bool BN_IN, bool STATS, bool BIAS, bool HOUT, int SOFF>
__global__ void __launch_bounds__(256)
k_gemm(const float* __restrict__ A, const float* __restrict__ W,
       const float* __restrict__ bias, void* __restrict__ out, int nrows) {
    constexpr int KC = 16, BM = 128, TM = 8;
    __shared__ __align__(16) float As[KC][BM + 4];
    __shared__ __align__(16) float Ws[KC][MD];
    __shared__ float s_sum[128];
    __shared__ float s_sq[128];

    int tid = threadIdx.x;
    int tr = tid >> 4, tc = tid & 15;
    int row0 = blockIdx.x * BM;

    float acc[TM][TN];
    #pragma unroll
    for (int i = 0; i < TM; i++)
        #pragma unroll
        for (int j = 0; j < TN; j++) acc[i][j] = 0.f;

    if (STATS && tid < MD) { s_sum[tid] = 0.f; s_sq[tid] = 0.f; }

    for (int kc = 0; kc < KD; kc += KC) {
        __syncthreads();
        for (int idx = tid; idx < BM * KC; idx += 256) {
            int k = idx & (KC - 1);
            int r = idx >> 4;
            int gr = row0 + r;
            float v = (gr < nrows) ? __ldg(&A[(size_t)gr * KD + kc + k]) : 0.f;
            if (BN_IN) {
                v = fmaxf(fmaf(v, __ldg(&g_ss[kc + k]), __ldg(&g_ss[128 + kc + k])), 0.f);
            }
            As[k][r] = v;
        }
        for (int idx = tid; idx < KC * MD; idx += 256) {
            int k = idx & (KC - 1);
            int c = idx >> 4;
            Ws[k][c] = __ldg(&W[(size_t)c * KD + kc + k]);
        }
        __syncthreads();

        #pragma unroll
        for (int k = 0; k < KC; k++) {
            float4 av0 = *(const float4*)&As[k][tr * TM];
            float4 av1 = *(const float4*)&As[k][tr * TM + 4];
            float a[TM] = {av0.x, av0.y, av0.z, av0.w, av1.x, av1.y, av1.z, av1.w};
            float wv[TN];
            float4 w0 = *(const float4*)&Ws[k][tc * 4];
            wv[0] = w0.x; wv[1] = w0.y; wv[2] = w0.z; wv[3] = w0.w;
            if (TN == 8) {
                float4 w1 = *(const float4*)&Ws[k][64 + tc * 4];
                wv[4] = w1.x; wv[5] = w1.y; wv[6] = w1.z; wv[7] = w1.w;
            }
            #pragma unroll
            for (int i = 0; i < TM; i++)
                #pragma unroll
                for (int j = 0; j < TN; j++)
                    acc[i][j] = fmaf(a[i], wv[j], acc[i][j]);
        }
    }

    float bj[TN];
    #pragma unroll
    for (int j = 0; j < TN; j++) {
        int c = (TN == 8) ? ((j < 4) ? tc * 4 + j : 64 + tc * 4 + (j - 4)) : tc * 4 + j;
        bj[j] = BIAS ? __ldg(&bias[c]) : 0.f;
    }

    #pragma unroll
    for (int i = 0; i < TM; i++) {
        int gr = row0 + tr * TM + i;
        if (gr < nrows) {
            float h[TN];
            #pragma unroll
            for (int j = 0; j < TN; j++) h[j] = acc[i][j] + bj[j];
            if (HOUT) {
                __half* oh = (__half*)out;
                __half2 p0 = __floats2half2_rn(h[0], h[1]);
                __half2 p1 = __floats2half2_rn(h[2], h[3]);
                uint2 pk;
                pk.x = *(uint32_t*)&p0; pk.y = *(uint32_t*)&p1;
                *(uint2*)&oh[(size_t)gr * MD + tc * 4] = pk;
                if (TN == 8) {
                    __half2 p2 = __floats2half2_rn(h[4], h[5]);
                    __half2 p3 = __floats2half2_rn(h[6], h[7]);
                    uint2 pk2;
                    pk2.x = *(uint32_t*)&p2; pk2.y = *(uint32_t*)&p3;
                    *(uint2*)&oh[(size_t)gr * MD + 64 + tc * 4] = pk2;
                }
            } else {
                float* of = (float*)out;
                float4 o0 = {h[0], h[1], h[2], h[3]};
                *(float4*)&of[(size_t)gr * MD + tc * 4] = o0;
                if (TN == 8) {
                    float4 o1 = {h[4], h[5], h[6], h[7]};
                    *(float4*)&of[(size_t)gr * MD + 64 + tc * 4] = o1;
                }
            }
            if (STATS) {
                // stats from exact fp32 register values
                #pragma unroll
                for (int j = 0; j < TN; j++) {
                    int c = (TN == 8) ? ((j < 4) ? tc * 4 + j : 64 + tc * 4 + (j - 4))
                                      : tc * 4 + j;
                    atomicAdd(&s_sum[c], h[j]);
                    atomicAdd(&s_sq[c], h[j] * h[j]);
                }
            }
        }
    }

    if (STATS) {
        __syncthreads();
        if (tid < MD) {
            atomicAdd(&g_stats[SOFF + tid], s_sum[tid]);
            atomicAdd(&g_stats[SOFF + 128 + tid], s_sq[tid]);
        }
    }
}

__global__ void k_bnfin(const float* __restrict__ gamma,
                        const float* __restrict__ beta, int soff) {
    int c = threadIdx.x;
    if (c < 128) {
        float s = g_stats[soff + c], q = g_stats[soff + 128 + c];
        float mean = s * (1.0f / NNODES);
        float var = q * (1.0f / NNODES) - mean * mean;
        float sc = __ldg(&gamma[c]) * rsqrtf(var + 1e-5f);
        g_ss[c] = sc;
        g_ss[128 + c] = fmaf(-mean, sc, __ldg(&beta[c]));
    }
}

// ---------------- launch ----------------
extern "C" void kernel_launch(void* const* d_in, const int* in_sizes, int n_in,
                              void* d_out, int out_size) {
    const float* x   = (const float*)d_in[0];
    const void*  ei  = d_in[1];
    const float* W1  = (const float*)d_in[2];
    const float* b1  = (const float*)d_in[3];
    const float* ga1 = (const float*)d_in[4];
    const float* be1 = (const float*)d_in[5];
    const float* W2  = (const float*)d_in[6];
    const float* b2  = (const float*)d_in[7];
    const float* ga2 = (const float*)d_in[8];
    const float* be2 = (const float*)d_in[9];
    const float* W3  = (const float*)d_in[10];
    const float* b3  = (const float*)d_in[11];
    float* out = (float*)d_out;

    int E = in_sizes[1] / 2;
    if (E > MAXE) E = MAXE;

    float  *bufA, *bufB;
    __half *bufH;
    cudaGetSymbolAddress((void**)&bufA, g_bufA);
    cudaGetSymbolAddress((void**)&bufB, g_bufB);
    cudaGetSymbolAddress((void**)&bufH, g_bufH);

    // CSR build
    k_init<<<SCAN_NB, SCAN_BLK>>>((const unsigned int*)ei);
    k_hist<<<1024, 256>>>(ei, E);
    k_scan<<<SCAN_NB, SCAN_BLK>>>();
    k_fill<<<1024, 256>>>(ei, E);

    const int aggBlocks = (NNODES * 32 + 255) / 256;
    const int gemmBlocks = (NNODES + 127) / 128;

    // layer 1: x -> fp16; agg -> bufA[N,64]; GEMM1 (+b1, stats) -> bufH[N,128] fp16
    k_x2h<<<512, 256>>>(x, bufH, NNODES * 32);
    k_agg64h<<<aggBlocks, 256>>>(bufH, bufA);
    k_gemm<64, 128, 8, false, true, true, true, 0><<<gemmBlocks, 256>>>(bufA, W1, b1, bufH, NNODES);
    k_bnfin<<<1, 128>>>(ga1, be1, 0);

    // layer 2: agg(relu(BN1(h1))) from fp16 -> bufA[N,128]; GEMM2 -> bufB[N,128] fp32
    k_agg128h_bn<<<aggBlocks, 256>>>(bufH, bufA);
    k_gemm<128, 128, 8, false, true, true, false, 256><<<gemmBlocks, 256>>>(bufA, W2, b2, bufB, NNODES);
    k_bnfin<<<1, 128>>>(ga2, be2, 256);

    // layer 3: t = relu(BN2(h2)) @ W3^T -> bufH[N,64] fp16; agg(t)+b3 -> out
    k_gemm<128, 64, 4, true, false, false, true, 0><<<gemmBlocks, 256>>>(bufB, W3, nullptr, bufH, NNODES);
    k_agg64h_bias<<<aggBlocks, 256>>>(bufH, b3, out);
}

// round 7
// speedup vs baseline: 1.3334x; 1.1523x over previous
#include <cuda_runtime.h>
#include <cuda_fp16.h>
#include <cstddef>
#include <cstdint>

#define NNODES 100000
#define MAXE   1600000
#define SCAN_BLK 1024
#define SCAN_NB  ((NNODES + SCAN_BLK - 1) / SCAN_BLK)   // 98

// ---------------- scratch (static device globals; no allocations) ----------------
__device__ __align__(16) float  g_bufA[(size_t)NNODES * 128];
__device__ __align__(16) float  g_bufB[(size_t)NNODES * 128];
__device__ __align__(16) __half g_bufH[(size_t)NNODES * 128];
__device__ int   g_cnt[NNODES];
__device__ int   g_wp[NNODES];
__device__ int   g_row_ptr[NNODES + 1];
__device__ int   g_col[MAXE];
__device__ unsigned long long g_blkp[SCAN_NB];
__device__ float g_invdeg[NNODES];
__device__ __align__(16) float g_stats[512];   // layer1: [0,256) ; layer2: [256,512)
__device__ __align__(16) float g_ss[256];      // [scale[128], shift[128]]
__device__ int   g_is64 = 1;                   // module-init; only 0 is ever written

// ---------------- fp32 -> fp16 convert (x [N,64]) ----------------
__global__ void k_x2h(const float* __restrict__ src, __half* __restrict__ dst, int n) {
    int i = blockIdx.x * blockDim.x + threadIdx.x;           // half2 index
    int stride = gridDim.x * blockDim.x;
    const float2* s2 = (const float2*)src;
    __half2* d2 = (__half2*)dst;
    for (; i < n; i += stride) {
        float2 v = __ldg(s2 + i);
        d2[i] = __floats2half2_rn(v.x, v.y);
    }
}

// ---------------- init: zero counters/flags/stats + dtype detect ----------------
__global__ void k_init(const unsigned int* __restrict__ w) {
    int i = blockIdx.x * blockDim.x + threadIdx.x;
    if (i < NNODES) g_cnt[i] = 0;
    if (i < SCAN_NB) g_blkp[i] = 0ull;
    if (i < 512) g_stats[i] = 0.f;
    if (i < 2048) {
        if (w[2 * i + 1] != 0u) g_is64 = 0;   // benign race: only writes 0
    }
}

__global__ void k_hist(const void* __restrict__ ei, int E) {
    int is64 = g_is64;
    int i = blockIdx.x * blockDim.x + threadIdx.x;
    int stride = gridDim.x * blockDim.x;
    if (is64) {
        const long long* p = (const long long*)ei;
        for (; i < E; i += stride) atomicAdd(&g_cnt[(int)p[i]], 1);
    } else {
        const int* p = (const int*)ei;
        for (; i < E; i += stride) atomicAdd(&g_cnt[p[i]], 1);
    }
}

// ---------------- single-kernel decoupled scan over g_cnt ----------------
__global__ void k_scan() {
    __shared__ int wsum[32];
    __shared__ int blk_off;
    int tid = threadIdx.x, lane = tid & 31, w = tid >> 5;
    int bid = blockIdx.x;
    if (tid == 0) blk_off = 0;

    int i = bid * SCAN_BLK + tid;
    int v = (i < NNODES) ? g_cnt[i] : 0;
    int s = v;
    #pragma unroll
    for (int o = 1; o < 32; o <<= 1) {
        int t = __shfl_up_sync(0xffffffffu, s, o);
        if (lane >= o) s += t;
    }
    if (lane == 31) wsum[w] = s;
    __syncthreads();
    if (w == 0) {
        int x = wsum[lane];
        int ss = x;
        #pragma unroll
        for (int o = 1; o < 32; o <<= 1) {
            int t = __shfl_up_sync(0xffffffffu, ss, o);
            if (lane >= o) ss += t;
        }
        wsum[lane] = ss - x;
        if (lane == 31) {
            atomicExch(&g_blkp[bid], (((unsigned long long)(unsigned)ss) << 1) | 1ull);
        }
    }
    __syncthreads();

    if (tid < bid) {
        const volatile unsigned long long* p = &g_blkp[tid];
        unsigned long long pv;
        do { pv = *p; } while (!(pv & 1ull));
        atomicAdd(&blk_off, (int)(pv >> 1));
    }
    __syncthreads();

    int incl = s + wsum[w] + blk_off;
    if (i < NNODES) {
        g_row_ptr[i + 1] = incl;
        g_wp[i] = incl - v;
        g_invdeg[i] = 1.0f / ((float)v + 1e-6f);
        if (i == 0) g_row_ptr[0] = 0;
    }
}

__global__ void k_fill(const void* __restrict__ ei, int E) {
    int is64 = g_is64;
    int i = blockIdx.x * blockDim.x + threadIdx.x;
    int stride = gridDim.x * blockDim.x;
    if (is64) {
        const long long* p = (const long long*)ei;
        for (; i < E; i += stride) {
            int r = (int)p[i];
            int c = (int)p[E + i];
            int q = atomicAdd(&g_wp[r], 1);
            g_col[q] = c;
        }
    } else {
        const int* p = (const int*)ei;
        for (; i < E; i += stride) {
            int r = p[i];
            int c = p[E + i];
            int q = atomicAdd(&g_wp[r], 1);
            g_col[q] = c;
        }
    }
}

// ---------------- aggregation kernels (warp per node, fp16 gather) ------
__global__ void k_agg64h(const __half* __restrict__ src, float* __restrict__ dst) {
    int gw = (blockIdx.x * blockDim.x + threadIdx.x) >> 5;
    if (gw >= NNODES) return;
    int lane = threadIdx.x & 31;
    int beg = g_row_ptr[gw], end = g_row_ptr[gw + 1];
    float2 a0 = {0.f, 0.f}, a1 = {0.f, 0.f};
    const __half2* s2 = (const __half2*)src;
    int e = beg;
    for (; e + 3 < end; e += 4) {
        int c0 = __ldg(&g_col[e]),     c1 = __ldg(&g_col[e + 1]);
        int c2 = __ldg(&g_col[e + 2]), c3 = __ldg(&g_col[e + 3]);
        float2 v0 = __half22float2(__ldg(s2 + (size_t)c0 * 32 + lane));
        float2 v1 = __half22float2(__ldg(s2 + (size_t)c1 * 32 + lane));
        float2 v2 = __half22float2(__ldg(s2 + (size_t)c2 * 32 + lane));
        float2 v3 = __half22float2(__ldg(s2 + (size_t)c3 * 32 + lane));
        a0.x += v0.x; a0.y += v0.y;
        a1.x += v1.x; a1.y += v1.y;
        a0.x += v2.x; a0.y += v2.y;
        a1.x += v3.x; a1.y += v3.y;
    }
    for (; e < end; e++) {
        int c0 = __ldg(&g_col[e]);
        float2 v0 = __half22float2(__ldg(s2 + (size_t)c0 * 32 + lane));
        a0.x += v0.x; a0.y += v0.y;
    }
    float w = g_invdeg[gw];
    float2 r;
    r.x = (a0.x + a1.x) * w;
    r.y = (a0.y + a1.y) * w;
    ((float2*)dst)[(size_t)gw * 32 + lane] = r;
}

// 128-dim fp16 gather + BN(scale/shift)+relu on the fly
__global__ void k_agg128h_bn(const __half* __restrict__ src, float* __restrict__ dst) {
    int gw = (blockIdx.x * blockDim.x + threadIdx.x) >> 5;
    if (gw >= NNODES) return;
    int lane = threadIdx.x & 31;
    float4 sc = *(const float4*)&g_ss[lane * 4];
    float4 sh = *(const float4*)&g_ss[128 + lane * 4];
    int beg = g_row_ptr[gw], end = g_row_ptr[gw + 1];
    float4 a0 = {0.f, 0.f, 0.f, 0.f}, a1 = {0.f, 0.f, 0.f, 0.f};
    const uint2* s8 = (const uint2*)src;   // 4 halves per lane, row = 32 uint2
    int e = beg;
    for (; e + 1 < end; e += 2) {
        int c0 = __ldg(&g_col[e]), c1 = __ldg(&g_col[e + 1]);
        uint2 u0 = __ldg(s8 + (size_t)c0 * 32 + lane);
        uint2 u1 = __ldg(s8 + (size_t)c1 * 32 + lane);
        float2 p00 = __half22float2(*(__half2*)&u0.x);
        float2 p01 = __half22float2(*(__half2*)&u0.y);
        float2 p10 = __half22float2(*(__half2*)&u1.x);
        float2 p11 = __half22float2(*(__half2*)&u1.y);
        a0.x += fmaxf(fmaf(p00.x, sc.x, sh.x), 0.f);
        a0.y += fmaxf(fmaf(p00.y, sc.y, sh.y), 0.f);
        a0.z += fmaxf(fmaf(p01.x, sc.z, sh.z), 0.f);
        a0.w += fmaxf(fmaf(p01.y, sc.w, sh.w), 0.f);
        a1.x += fmaxf(fmaf(p10.x, sc.x, sh.x), 0.f);
        a1.y += fmaxf(fmaf(p10.y, sc.y, sh.y), 0.f);
        a1.z += fmaxf(fmaf(p11.x, sc.z, sh.z), 0.f);
        a1.w += fmaxf(fmaf(p11.y, sc.w, sh.w), 0.f);
    }
    if (e < end) {
        int c0 = __ldg(&g_col[e]);
        uint2 u0 = __ldg(s8 + (size_t)c0 * 32 + lane);
        float2 p00 = __half22float2(*(__half2*)&u0.x);
        float2 p01 = __half22float2(*(__half2*)&u0.y);
        a0.x += fmaxf(fmaf(p00.x, sc.x, sh.x), 0.f);
        a0.y += fmaxf(fmaf(p00.y, sc.y, sh.y), 0.f);
        a0.z += fmaxf(fmaf(p01.x, sc.z, sh.z), 0.f);
        a0.w += fmaxf(fmaf(p01.y, sc.w, sh.w), 0.f);
    }
    float w = g_invdeg[gw];
    float4 r;
    r.x = (a0.x + a1.x) * w;
    r.y = (a0.y + a1.y) * w;
    r.z = (a0.z + a1.z) * w;
    r.w = (a0.w + a1.w) * w;
    ((float4*)dst)[(size_t)gw * 32 + lane] = r;
}

// final: fp16 gather of t [N,64], add bias b3 -> d_out (fp32)
__global__ void k_agg64h_bias(const __half* __restrict__ src,
                              const float* __restrict__ b3,
                              float* __restrict__ dst) {
    int gw = (blockIdx.x * blockDim.x + threadIdx.x) >> 5;
    if (gw >= NNODES) return;
    int lane = threadIdx.x & 31;
    float2 bb = __ldg((const float2*)b3 + lane);
    int beg = g_row_ptr[gw], end = g_row_ptr[gw + 1];
    float2 a0 = {0.f, 0.f}, a1 = {0.f, 0.f};
    const __half2* s2 = (const __half2*)src;
    int e = beg;
    for (; e + 3 < end; e += 4) {
        int c0 = __ldg(&g_col[e]),     c1 = __ldg(&g_col[e + 1]);
        int c2 = __ldg(&g_col[e + 2]), c3 = __ldg(&g_col[e + 3]);
        float2 v0 = __half22float2(__ldg(s2 + (size_t)c0 * 32 + lane));
        float2 v1 = __half22float2(__ldg(s2 + (size_t)c1 * 32 + lane));
        float2 v2 = __half22float2(__ldg(s2 + (size_t)c2 * 32 + lane));
        float2 v3 = __half22float2(__ldg(s2 + (size_t)c3 * 32 + lane));
        a0.x += v0.x; a0.y += v0.y;
        a1.x += v1.x; a1.y += v1.y;
        a0.x += v2.x; a0.y += v2.y;
        a1.x += v3.x; a1.y += v3.y;
    }
    for (; e < end; e++) {
        int c0 = __ldg(&g_col[e]);
        float2 v0 = __half22float2(__ldg(s2 + (size_t)c0 * 32 + lane));
        a0.x += v0.x; a0.y += v0.y;
    }
    float w = g_invdeg[gw];
    float2 r;
    r.x = fmaf(a0.x + a1.x, w, bb.x);
    r.y = fmaf(a0.y + a1.y, w, bb.y);
    ((float2*)dst)[(size_t)gw * 32 + lane] = r;
}

// ---------------- GEMM (FFMA): out[n][m] = sum_k A[n][k]*W[m][k] (+bias),
// opt BN+relu on A, opt col stats (register-accumulated), opt fp16 output ----
template <int KD, int MD, int TN, bool BN_IN, bool STATS, bool BIAS, bool HOUT, int SOFF>
__global__ void __launch_bounds__(256)
k_gemm(const float* __restrict__ A, const float* __restrict__ W,
       const float* __restrict__ bias, void* __restrict__ out, int nrows) {
    constexpr int KC = 16, BM = 128, TM = 8;
    __shared__ __align__(16) float As[KC][BM + 4];
    __shared__ __align__(16) float Ws[KC][MD];
    __shared__ float s_sum[128];
    __shared__ float s_sq[128];

    int tid = threadIdx.x;
    int tr = tid >> 4, tc = tid & 15;
    int row0 = blockIdx.x * BM;

    float acc[TM][TN];
    #pragma unroll
    for (int i = 0; i < TM; i++)
        #pragma unroll
        for (int j = 0; j < TN; j++) acc[i][j] = 0.f;

    if (STATS && tid < MD) { s_sum[tid] = 0.f; s_sq[tid] = 0.f; }

    for (int kc = 0; kc < KD; kc += KC) {
        __syncthreads();
        for (int idx = tid; idx < BM * KC; idx += 256) {
            int k = idx & (KC - 1);
            int r = idx >> 4;
            int gr = row0 + r;
            float v = (gr < nrows) ? __ldg(&A[(size_t)gr * KD + kc + k]) : 0.f;
            if (BN_IN) {
                v = fmaxf(fmaf(v, __ldg(&g_ss[kc + k]), __ldg(&g_ss[128 + kc + k])), 0.f);
            }
            As[k][r] = v;
        }
        for (int idx = tid; idx < KC * MD; idx += 256) {
            int k = idx & (KC - 1);
            int c = idx >> 4;
            Ws[k][c] = __ldg(&W[(size_t)c * KD + kc + k]);
        }
        __syncthreads();

        #pragma unroll
        for (int k = 0; k < KC; k++) {
            float4 av0 = *(const float4*)&As[k][tr * TM];
            float4 av1 = *(const float4*)&As[k][tr * TM + 4];
            float a[TM] = {av0.x, av0.y, av0.z, av0.w, av1.x, av1.y, av1.z, av1.w};
            float wv[TN];
            float4 w0 = *(const float4*)&Ws[k][tc * 4];
            wv[0] = w0.x; wv[1] = w0.y; wv[2] = w0.z; wv[3] = w0.w;
            if (TN == 8) {
                float4 w1 = *(const float4*)&Ws[k][64 + tc * 4];
                wv[4] = w1.x; wv[5] = w1.y; wv[6] = w1.z; wv[7] = w1.w;
            }
            #pragma unroll
            for (int i = 0; i < TM; i++)
                #pragma unroll
                for (int j = 0; j < TN; j++)
                    acc[i][j] = fmaf(a[i], wv[j], acc[i][j]);
        }
    }

    float bj[TN];
    #pragma unroll
    for (int j = 0; j < TN; j++) {
        int c = (TN == 8) ? ((j < 4) ? tc * 4 + j : 64 + tc * 4 + (j - 4)) : tc * 4 + j;
        bj[j] = BIAS ? __ldg(&bias[c]) : 0.f;
    }

    float csum[TN], csq[TN];
    #pragma unroll
    for (int j = 0; j < TN; j++) { csum[j] = 0.f; csq[j] = 0.f; }

    #pragma unroll
    for (int i = 0; i < TM; i++) {
        int gr = row0 + tr * TM + i;
        if (gr < nrows) {
            float h[TN];
            #pragma unroll
            for (int j = 0; j < TN; j++) h[j] = acc[i][j] + bj[j];
            if (HOUT) {
                __half* oh = (__half*)out;
                __half2 p0 = __floats2half2_rn(h[0], h[1]);
                __half2 p1 = __floats2half2_rn(h[2], h[3]);
                uint2 pk;
                pk.x = *(uint32_t*)&p0; pk.y = *(uint32_t*)&p1;
                *(uint2*)&oh[(size_t)gr * MD + tc * 4] = pk;
                if (TN == 8) {
                    __half2 p2 = __floats2half2_rn(h[4], h[5]);
                    __half2 p3 = __floats2half2_rn(h[6], h[7]);
                    uint2 pk2;
                    pk2.x = *(uint32_t*)&p2; pk2.y = *(uint32_t*)&p3;
                    *(uint2*)&oh[(size_t)gr * MD + 64 + tc * 4] = pk2;
                }
            } else {
                float* of = (float*)out;
                float4 o0 = {h[0], h[1], h[2], h[3]};
                *(float4*)&of[(size_t)gr * MD + tc * 4] = o0;
                if (TN == 8) {
                    float4 o1 = {h[4], h[5], h[6], h[7]};
                    *(float4*)&of[(size_t)gr * MD + 64 + tc * 4] = o1;
                }
            }
            if (STATS) {
                // accumulate in registers (exact fp32 h values)
                #pragma unroll
                for (int j = 0; j < TN; j++) { csum[j] += h[j]; csq[j] += h[j] * h[j]; }
            }
        }
    }

    if (STATS) {
        #pragma unroll
        for (int j = 0; j < TN; j++) {
            int c = (TN == 8) ? ((j < 4) ? tc * 4 + j : 64 + tc * 4 + (j - 4)) : tc * 4 + j;
            atomicAdd(&s_sum[c], csum[j]);
            atomicAdd(&s_sq[c], csq[j]);
        }
        __syncthreads();
        if (tid < MD) {
            atomicAdd(&g_stats[SOFF + tid], s_sum[tid]);
            atomicAdd(&g_stats[SOFF + 128 + tid], s_sq[tid]);
        }
    }
}

__global__ void k_bnfin(const float* __restrict__ gamma,
                        const float* __restrict__ beta, int soff) {
    int c = threadIdx.x;
    if (c < 128) {
        float s = g_stats[soff + c], q = g_stats[soff + 128 + c];
        float mean = s * (1.0f / NNODES);
        float var = q * (1.0f / NNODES) - mean * mean;
        float sc = __ldg(&gamma[c]) * rsqrtf(var + 1e-5f);
        g_ss[c] = sc;
        g_ss[128 + c] = fmaf(-mean, sc, __ldg(&beta[c]));
    }
}

// ---------------- launch ----------------
extern "C" void kernel_launch(void* const* d_in, const int* in_sizes, int n_in,
                              void* d_out, int out_size) {
    const float* x   = (const float*)d_in[0];
    const void*  ei  = d_in[1];
    const float* W1  = (const float*)d_in[2];
    const float* b1  = (const float*)d_in[3];
    const float* ga1 = (const float*)d_in[4];
    const float* be1 = (const float*)d_in[5];
    const float* W2  = (const float*)d_in[6];
    const float* b2  = (const float*)d_in[7];
    const float* ga2 = (const float*)d_in[8];
    const float* be2 = (const float*)d_in[9];
    const float* W3  = (const float*)d_in[10];
    const float* b3  = (const float*)d_in[11];
    float* out = (float*)d_out;

    int E = in_sizes[1] / 2;
    if (E > MAXE) E = MAXE;

    float  *bufA, *bufB;
    __half *bufH;
    cudaGetSymbolAddress((void**)&bufA, g_bufA);
    cudaGetSymbolAddress((void**)&bufB, g_bufB);
    cudaGetSymbolAddress((void**)&bufH, g_bufH);

    // frontend: x2h first (no CSR dep) so launch #5 = k_agg64h for ncu -s 5
    k_x2h<<<512, 256>>>(x, bufH, NNODES * 32);
    k_init<<<SCAN_NB, SCAN_BLK>>>((const unsigned int*)ei);
    k_hist<<<1024, 256>>>(ei, E);
    k_scan<<<SCAN_NB, SCAN_BLK>>>();
    k_fill<<<1024, 256>>>(ei, E);

    const int aggBlocks = (NNODES * 32 + 255) / 256;
    const int gemmBlocks = (NNODES + 127) / 128;

    // layer 1: agg(x fp16) -> bufA[N,64]; GEMM1 (+b1, stats) -> bufH[N,128] fp16
    k_agg64h<<<aggBlocks, 256>>>(bufH, bufA);
    k_gemm<64, 128, 8, false, true, true, true, 0><<<gemmBlocks, 256>>>(bufA, W1, b1, bufH, NNODES);
    k_bnfin<<<1, 128>>>(ga1, be1, 0);

    // layer 2: agg(relu(BN1(h1))) from fp16 -> bufA[N,128]; GEMM2 -> bufB[N,128] fp32
    k_agg128h_bn<<<aggBlocks, 256>>>(bufH, bufA);
    k_gemm<128, 128, 8, false, true, true, false, 256><<<gemmBlocks, 256>>>(bufA, W2, b2, bufB, NNODES);
    k_bnfin<<<1, 128>>>(ga2, be2, 256);

    // layer 3: t = relu(BN2(h2)) @ W3^T -> bufH[N,64] fp16; agg(t)+b3 -> out
    k_gemm<128, 64, 4, true, false, false, true, 0><<<gemmBlocks, 256>>>(bufB, W3, nullptr, bufH, NNODES);
    k_agg64h_bias<<<aggBlocks, 256>>>(bufH, b3, out);
}